// round 12
// baseline (speedup 1.0000x reference)
#include <cuda_runtime.h>
#include <cuda_fp16.h>
#include <mma.h>

using namespace nvcuda;

#define D_FEAT  128
#define HIDDEN  256
#define NOUT    512      // 2*HIDDEN (A and B halves)
#define MAX_NODES 100000

// Precomputed per-node tables (fp16): A' = W1a*h + b1, B = W1b*h
__device__ __half g_A[(size_t)MAX_NODES * HIDDEN];   // 51.2 MB
__device__ __half g_B[(size_t)MAX_NODES * HIDDEN];   // 51.2 MB
__device__ __half g_W[D_FEAT * NOUT];                // Wcat[k][j], 128 KB

// ---------------------------------------------------------------------------
// Prep: Wcat[k][j] = W1_w[j][k] (j<256) | W1_w[j-256][128+k] (j>=256)
// ---------------------------------------------------------------------------
__global__ void prep_w_kernel(const float* __restrict__ W1) {
    int idx = blockIdx.x * blockDim.x + threadIdx.x;
    if (idx >= D_FEAT * NOUT) return;
    int k = idx / NOUT;
    int j = idx % NOUT;
    float v = (j < HIDDEN) ? W1[(size_t)j * (2 * D_FEAT) + k]
                           : W1[(size_t)(j - HIDDEN) * (2 * D_FEAT) + D_FEAT + k];
    g_W[(size_t)k * NOUT + j] = __float2half(v);
}

// ---------------------------------------------------------------------------
// Precompute GEMM (R9, proven): warp tile 32x64, cp.async W prefetch.
// Block = 128 rows; 2 slices of 128 cols (grid.y = 2 -> A-pair / B-pair).
// ---------------------------------------------------------------------------
#define MT 128
#define SLD 136
#define TILE_B (MT * SLD * 2)   // 34816

__global__ void __launch_bounds__(256, 2) gemm_ab_kernel(
    const float* __restrict__ h, const float* __restrict__ b1, int n_nodes)
{
    extern __shared__ char dsm[];
    __half* sA  = reinterpret_cast<__half*>(dsm);
    __half* sW0 = reinterpret_cast<__half*>(dsm + TILE_B);
    __half* sW1 = reinterpret_cast<__half*>(dsm + 2 * TILE_B);

    int mBase = blockIdx.x * MT;
    int wid  = threadIdx.x >> 5;
    int wm   = (wid & 3) * 32;
    int wn   = (wid >> 2) * 64;

    int nSlice0 = blockIdx.y * 256;
    int nSlice1 = nSlice0 + 128;

    for (int i = threadIdx.x; i < MT * (D_FEAT / 4); i += 256) {
        int r  = i >> 5;
        int c4 = i & 31;
        float4 v = make_float4(0.f, 0.f, 0.f, 0.f);
        int row = mBase + r;
        if (row < n_nodes) v = *(const float4*)(h + (size_t)row * D_FEAT + c4 * 4);
        __half2 lo = __floats2half2_rn(v.x, v.y);
        __half2 hi = __floats2half2_rn(v.z, v.w);
        uint2 pk;
        pk.x = *(const unsigned*)&lo;
        pk.y = *(const unsigned*)&hi;
        *(uint2*)(&sA[r * SLD + c4 * 4]) = pk;
    }

    for (int i = threadIdx.x; i < MT * 16; i += 256) {
        int k  = i >> 4;
        int c8 = i & 15;
        *(uint4*)(&sW0[k * SLD + c8 * 8]) =
            *(const uint4*)(g_W + (size_t)k * NOUT + nSlice0 + c8 * 8);
    }

    for (int i = threadIdx.x; i < MT * 16; i += 256) {
        int k  = i >> 4;
        int c8 = i & 15;
        unsigned saddr = (unsigned)__cvta_generic_to_shared(&sW1[k * SLD + c8 * 8]);
        const void* gp = g_W + (size_t)k * NOUT + nSlice1 + c8 * 8;
        asm volatile("cp.async.ca.shared.global [%0], [%1], 16;\n"
                     :: "r"(saddr), "l"(gp));
    }
    asm volatile("cp.async.commit_group;\n");

    __syncthreads();

    float* sC = reinterpret_cast<float*>(sW0);

#pragma unroll
    for (int k2 = 0; k2 < 2; k2++) {
        const __half* sW = (k2 == 0) ? sW0 : sW1;
        int nSlice = (k2 == 0) ? nSlice0 : nSlice1;

        wmma::fragment<wmma::accumulator, 16, 16, 16, float> acc[2][4];
#pragma unroll
        for (int i = 0; i < 2; i++)
#pragma unroll
            for (int j = 0; j < 4; j++) wmma::fill_fragment(acc[i][j], 0.0f);

#pragma unroll
        for (int k = 0; k < D_FEAT; k += 16) {
            wmma::fragment<wmma::matrix_a, 16, 16, 16, __half, wmma::row_major> fa[2];
            wmma::load_matrix_sync(fa[0], &sA[(wm     ) * SLD + k], SLD);
            wmma::load_matrix_sync(fa[1], &sA[(wm + 16) * SLD + k], SLD);
#pragma unroll
            for (int j = 0; j < 4; j++) {
                wmma::fragment<wmma::matrix_b, 16, 16, 16, __half, wmma::row_major> fb;
                wmma::load_matrix_sync(fb, &sW[k * SLD + wn + j * 16], SLD);
                wmma::mma_sync(acc[0][j], fa[0], fb, acc[0][j]);
                wmma::mma_sync(acc[1][j], fa[1], fb, acc[1][j]);
            }
        }

        bool isA = (nSlice < HIDDEN);
        __half* gOut = isA ? g_A : g_B;
        int jBase = isA ? nSlice : (nSlice - HIDDEN);

#pragma unroll
        for (int p = 0; p < 2; p++) {
            __syncthreads();
            if ((wid >> 2) == p) {
#pragma unroll
                for (int i = 0; i < 2; i++)
#pragma unroll
                    for (int j = 0; j < 4; j++)
                        wmma::store_matrix_sync(
                            sC + (size_t)(wm + i * 16) * 68 + j * 16,
                            acc[i][j], 68, wmma::mem_row_major);
            }
            __syncthreads();

            for (int i = threadIdx.x; i < MT * 8; i += 256) {
                int r = i >> 3;
                int g = i & 7;
                int row = mBase + r;
                if (row >= n_nodes) continue;
                int j = jBase + p * 64 + g * 8;
                const float* q = sC + (size_t)r * 68 + g * 8;
                float v0 = q[0], v1 = q[1], v2 = q[2], v3 = q[3];
                float v4 = q[4], v5 = q[5], v6 = q[6], v7 = q[7];
                if (isA) {
                    float4 ba = *(const float4*)(b1 + j);
                    float4 bb = *(const float4*)(b1 + j + 4);
                    v0 += ba.x; v1 += ba.y; v2 += ba.z; v3 += ba.w;
                    v4 += bb.x; v5 += bb.y; v6 += bb.z; v7 += bb.w;
                }
                __half2 h0 = __floats2half2_rn(v0, v1);
                __half2 h1 = __floats2half2_rn(v2, v3);
                __half2 h2 = __floats2half2_rn(v4, v5);
                __half2 h3 = __floats2half2_rn(v6, v7);
                uint4 pk;
                pk.x = *(const unsigned*)&h0; pk.y = *(const unsigned*)&h1;
                pk.z = *(const unsigned*)&h2; pk.w = *(const unsigned*)&h3;
                *(uint4*)(gOut + (size_t)row * HIDDEN + j) = pk;
            }
        }

        if (k2 == 0) {
            asm volatile("cp.async.wait_group 0;\n");
            __syncthreads();
        }
    }
}

// ---------------------------------------------------------------------------
// Edge kernel with dst-range pass filter (L2 cache partitioning):
// only edges whose dst falls in [dstLo, dstHi) are processed this pass.
// Per pass the hot set = A (51.2 MB) + B-half (25.6 MB) < L2 (126 MB),
// so B-half is L2-resident and DRAM thrash collapses.
// Activity test is warp-uniform -> clean predication, no divergence.
// ---------------------------------------------------------------------------
__device__ __forceinline__ uint4 ldg_cg_128(const void* p) {
    uint4 v;
    asm("ld.global.cg.v4.u32 {%0,%1,%2,%3}, [%4];"
        : "=r"(v.x), "=r"(v.y), "=r"(v.z), "=r"(v.w) : "l"(p));
    return v;
}

#define KE 4   // edges per warp

__global__ void __launch_bounds__(256) edge_kernel(
    const int* __restrict__ src, const int* __restrict__ dst,
    const float* __restrict__ W2, const float* __restrict__ b2,
    float* __restrict__ out, int E, int dstLo, int dstHi)
{
    __shared__ float sW[HIDDEN];
    __shared__ float sb2;
    for (int i = threadIdx.x; i < HIDDEN; i += 256) sW[i] = W2[i];
    if (threadIdx.x == 0) sb2 = b2[0];
    __syncthreads();

    int lane = threadIdx.x & 31;
    int warp = threadIdx.x >> 5;
    int eb = (blockIdx.x * 8 + warp) * KE;
    if (eb >= E) return;

    float w[8];
#pragma unroll
    for (int i = 0; i < 8; i++) w[i] = sW[lane * 8 + i];

    int s[KE], d[KE];
    bool act[KE];
#pragma unroll
    for (int i = 0; i < KE; i++) {
        int e = eb + i;
        int ec = (e < E) ? e : (E - 1);
        s[i] = __ldg(src + ec);
        d[i] = __ldg(dst + ec);
        act[i] = (e < E) && (d[i] >= dstLo) && (d[i] < dstHi);
    }

    // Issue gathers only for this pass's edges (warp-uniform predicates)
    uint4 va[KE], vb[KE];
#pragma unroll
    for (int i = 0; i < KE; i++) {
        if (act[i]) {
            va[i] = ldg_cg_128(g_A + (size_t)s[i] * HIDDEN + lane * 8);
            vb[i] = ldg_cg_128(g_B + (size_t)d[i] * HIDDEN + lane * 8);
        }
    }

    const __half2 zero2 = __float2half2_rn(0.f);

#pragma unroll
    for (int i = 0; i < KE; i++) {
        if (!act[i]) continue;
        const __half2* pa = (const __half2*)&va[i];
        const __half2* pb = (const __half2*)&vb[i];
        float acc = 0.f;
#pragma unroll
        for (int q = 0; q < 4; q++) {
            __half2 z2 = __hmax2(__hadd2(pa[q], pb[q]), zero2);
            float2 f = __half22float2(z2);
            acc = fmaf(f.x, w[2 * q + 0], acc);
            acc = fmaf(f.y, w[2 * q + 1], acc);
        }
#pragma unroll
        for (int off = 16; off > 0; off >>= 1)
            acc += __shfl_xor_sync(0xFFFFFFFFu, acc, off);
        if (lane == 0) out[eb + i] = acc + sb2;
    }
}

// ---------------------------------------------------------------------------
extern "C" void kernel_launch(void* const* d_in, const int* in_sizes, int n_in,
                              void* d_out, int out_size)
{
    const float* h    = (const float*)d_in[0];
    const int*   src  = (const int*)d_in[1];
    const int*   dst  = (const int*)d_in[2];
    const float* W1_w = (const float*)d_in[3];
    const float* W1_b = (const float*)d_in[4];
    const float* W2_w = (const float*)d_in[5];
    const float* W2_b = (const float*)d_in[6];
    float* out = (float*)d_out;

    int n_nodes = in_sizes[0] / D_FEAT;
    int E = in_sizes[1];

    // 1) Weight reorder
    prep_w_kernel<<<(D_FEAT * NOUT + 255) / 256, 256>>>(W1_w);

    // 2) Precompute A' (with b1) and B per node — 102 KB dynamic smem
    static int smem_set = 0;
    int smem_bytes = 3 * TILE_B;
    if (!smem_set) {
        cudaFuncSetAttribute(gemm_ab_kernel,
                             cudaFuncAttributeMaxDynamicSharedMemorySize,
                             smem_bytes);
        smem_set = 1;
    }
    dim3 ggrid((n_nodes + MT - 1) / MT, 2);
    gemm_ab_kernel<<<ggrid, 256, smem_bytes>>>(h, W1_b, n_nodes);

    // 3) Per-edge, two dst-range passes (keeps B-half + A in L2 per pass)
    int edges_per_block = 8 * KE;
    int grid = (E + edges_per_block - 1) / edges_per_block;
    int half = n_nodes / 2;
    edge_kernel<<<grid, 256>>>(src, dst, W2_w, W2_b, out, E, 0, half);
    edge_kernel<<<grid, 256>>>(src, dst, W2_w, W2_b, out, E, half, n_nodes);
}

// round 13
// speedup vs baseline: 2.5953x; 2.5953x over previous
#include <cuda_runtime.h>
#include <cuda_fp16.h>
#include <mma.h>

using namespace nvcuda;

#define D_FEAT  128
#define HIDDEN  256
#define NOUT    512      // 2*HIDDEN (A and B halves)
#define MAX_NODES 100000

// Precomputed per-node tables (fp16): A' = W1a*h + b1, B = W1b*h
__device__ __half g_A[(size_t)MAX_NODES * HIDDEN];   // 51.2 MB
__device__ __half g_B[(size_t)MAX_NODES * HIDDEN];   // 51.2 MB
__device__ __half g_W[D_FEAT * NOUT];                // Wcat[k][j], 128 KB

// ---------------------------------------------------------------------------
// Prep: Wcat[k][j] = W1_w[j][k] (j<256) | W1_w[j-256][128+k] (j>=256)
// ---------------------------------------------------------------------------
__global__ void prep_w_kernel(const float* __restrict__ W1) {
    int idx = blockIdx.x * blockDim.x + threadIdx.x;
    if (idx >= D_FEAT * NOUT) return;
    int k = idx / NOUT;
    int j = idx % NOUT;
    float v = (j < HIDDEN) ? W1[(size_t)j * (2 * D_FEAT) + k]
                           : W1[(size_t)(j - HIDDEN) * (2 * D_FEAT) + D_FEAT + k];
    g_W[(size_t)k * NOUT + j] = __float2half(v);
}

// ---------------------------------------------------------------------------
// Precompute GEMM: C[n,512] = h[n,128] @ Wcat[128,512], fp32 accumulate.
// ONE block per 128 rows; 4 N-slices of 128 cols serially. W double-buffered
// via cp.async with rotation: slice s in buf[s%2]; after compute(s) the
// buffer doubles as fp32 epilogue staging, then receives slice s+2.
// h is read ONCE. smem: sA + buf0 + buf1 = 104448 B, 2 CTAs/SM.
// ---------------------------------------------------------------------------
#define MT 128
#define SLD 136
#define TILE_B (MT * SLD * 2)   // 34816

__device__ __forceinline__ void cp_async_16(void* smem_dst, const void* gptr) {
    unsigned saddr = (unsigned)__cvta_generic_to_shared(smem_dst);
    asm volatile("cp.async.ca.shared.global [%0], [%1], 16;\n"
                 :: "r"(saddr), "l"(gptr));
}

__global__ void __launch_bounds__(256, 2) gemm_ab_kernel(
    const float* __restrict__ h, const float* __restrict__ b1, int n_nodes)
{
    extern __shared__ char dsm[];
    __half* sA = reinterpret_cast<__half*>(dsm);
    __half* buf[2] = { reinterpret_cast<__half*>(dsm + TILE_B),
                       reinterpret_cast<__half*>(dsm + 2 * TILE_B) };

    int mBase = blockIdx.x * MT;
    int wid  = threadIdx.x >> 5;
    int wm   = (wid & 3) * 32;     // warp rows within tile
    int wn   = (wid >> 2) * 64;    // warp cols within slice

    // --- issue W slice 0 and 1 prefetches (groups G0, G1) ---
    for (int s = 0; s < 2; s++) {
        __half* dst = buf[s];
        for (int i = threadIdx.x; i < MT * 16; i += 256) {
            int k  = i >> 4;
            int c8 = i & 15;
            cp_async_16(&dst[k * SLD + c8 * 8],
                        g_W + (size_t)k * NOUT + s * 128 + c8 * 8);
        }
        asm volatile("cp.async.commit_group;\n");
    }

    // --- load h tile (fp32 -> fp16), overlapped with W prefetch flight ---
    for (int i = threadIdx.x; i < MT * (D_FEAT / 4); i += 256) {
        int r  = i >> 5;
        int c4 = i & 31;
        float4 v = make_float4(0.f, 0.f, 0.f, 0.f);
        int row = mBase + r;
        if (row < n_nodes) v = *(const float4*)(h + (size_t)row * D_FEAT + c4 * 4);
        __half2 lo = __floats2half2_rn(v.x, v.y);
        __half2 hi = __floats2half2_rn(v.z, v.w);
        uint2 pk;
        pk.x = *(const unsigned*)&lo;
        pk.y = *(const unsigned*)&hi;
        *(uint2*)(&sA[r * SLD + c4 * 4]) = pk;
    }

#pragma unroll
    for (int s = 0; s < 4; s++) {
        __half* sW = buf[s & 1];

        // Wait for this slice's W (in-order group completion): allow at most
        // one pending group (the next slice's) to remain in flight.
        if (s < 3) asm volatile("cp.async.wait_group 1;\n");
        else       asm volatile("cp.async.wait_group 0;\n");
        __syncthreads();   // sW visible (and sA on s=0; staging free later)

        wmma::fragment<wmma::accumulator, 16, 16, 16, float> acc[2][4];
#pragma unroll
        for (int i = 0; i < 2; i++)
#pragma unroll
            for (int j = 0; j < 4; j++) wmma::fill_fragment(acc[i][j], 0.0f);

#pragma unroll
        for (int k = 0; k < D_FEAT; k += 16) {
            wmma::fragment<wmma::matrix_a, 16, 16, 16, __half, wmma::row_major> fa[2];
            wmma::load_matrix_sync(fa[0], &sA[(wm     ) * SLD + k], SLD);
            wmma::load_matrix_sync(fa[1], &sA[(wm + 16) * SLD + k], SLD);
#pragma unroll
            for (int j = 0; j < 4; j++) {
                wmma::fragment<wmma::matrix_b, 16, 16, 16, __half, wmma::row_major> fb;
                wmma::load_matrix_sync(fb, &sW[k * SLD + wn + j * 16], SLD);
                wmma::mma_sync(acc[0][j], fa[0], fb, acc[0][j]);
                wmma::mma_sync(acc[1][j], fa[1], fb, acc[1][j]);
            }
        }

        bool isA = (s < 2);
        __half* gOut = isA ? g_A : g_B;
        int jBase = (isA ? s : (s - 2)) * 128;

        // Epilogue: two 64-col passes staged through this slice's W buffer
        // (128 x 68 fp32 = 34816 B, exactly TILE_B).
        float* sC = reinterpret_cast<float*>(sW);
#pragma unroll
        for (int p = 0; p < 2; p++) {
            __syncthreads();   // compute reads of sW done (p=0) / prior pass (p=1)
            if ((wid >> 2) == p) {
#pragma unroll
                for (int i = 0; i < 2; i++)
#pragma unroll
                    for (int j = 0; j < 4; j++)
                        wmma::store_matrix_sync(
                            sC + (size_t)(wm + i * 16) * 68 + j * 16,
                            acc[i][j], 68, wmma::mem_row_major);
            }
            __syncthreads();

            for (int i = threadIdx.x; i < MT * 8; i += 256) {
                int r = i >> 3;
                int g = i & 7;
                int row = mBase + r;
                if (row >= n_nodes) continue;
                int j = jBase + p * 64 + g * 8;
                const float* q = sC + (size_t)r * 68 + g * 8;
                float v0 = q[0], v1 = q[1], v2 = q[2], v3 = q[3];
                float v4 = q[4], v5 = q[5], v6 = q[6], v7 = q[7];
                if (isA) {
                    float4 ba = *(const float4*)(b1 + j);
                    float4 bb = *(const float4*)(b1 + j + 4);
                    v0 += ba.x; v1 += ba.y; v2 += ba.z; v3 += ba.w;
                    v4 += bb.x; v5 += bb.y; v6 += bb.z; v7 += bb.w;
                }
                __half2 h0 = __floats2half2_rn(v0, v1);
                __half2 h1 = __floats2half2_rn(v2, v3);
                __half2 h2 = __floats2half2_rn(v4, v5);
                __half2 h3 = __floats2half2_rn(v6, v7);
                uint4 pk;
                pk.x = *(const unsigned*)&h0; pk.y = *(const unsigned*)&h1;
                pk.z = *(const unsigned*)&h2; pk.w = *(const unsigned*)&h3;
                *(uint4*)(gOut + (size_t)row * HIDDEN + j) = pk;
            }
        }

        // Refill this buffer with W slice s+2 (epilogue reads done after the
        // barrier inside the last pass; add one to order the refill).
        if (s < 2) {
            __syncthreads();   // all epilogue smem reads of sC complete
            __half* dst = buf[s & 1];
            int nB = (s + 2) * 128;
            for (int i = threadIdx.x; i < MT * 16; i += 256) {
                int k  = i >> 4;
                int c8 = i & 15;
                cp_async_16(&dst[k * SLD + c8 * 8],
                            g_W + (size_t)k * NOUT + nB + c8 * 8);
            }
            asm volatile("cp.async.commit_group;\n");
        }
    }
}

// ---------------------------------------------------------------------------
// Edge kernel (R9, proven ~156us): 1 edge/warp, 4 edges batched, coalesced
// LDG.128, .cg table gathers, MLP=8.
// ---------------------------------------------------------------------------
__device__ __forceinline__ uint4 ldg_cg_128(const void* p) {
    uint4 v;
    asm("ld.global.cg.v4.u32 {%0,%1,%2,%3}, [%4];"
        : "=r"(v.x), "=r"(v.y), "=r"(v.z), "=r"(v.w) : "l"(p));
    return v;
}

#define KE 4

__global__ void __launch_bounds__(256) edge_kernel(
    const int* __restrict__ src, const int* __restrict__ dst,
    const float* __restrict__ W2, const float* __restrict__ b2,
    float* __restrict__ out, int E)
{
    __shared__ float sW[HIDDEN];
    __shared__ float sb2;
    for (int i = threadIdx.x; i < HIDDEN; i += 256) sW[i] = W2[i];
    if (threadIdx.x == 0) sb2 = b2[0];
    __syncthreads();

    int lane = threadIdx.x & 31;
    int warp = threadIdx.x >> 5;
    int eb = (blockIdx.x * 8 + warp) * KE;
    if (eb >= E) return;

    float w[8];
#pragma unroll
    for (int i = 0; i < 8; i++) w[i] = sW[lane * 8 + i];

    int s[KE], d[KE];
#pragma unroll
    for (int i = 0; i < KE; i++) {
        int e = eb + i;
        int ec = (e < E) ? e : (E - 1);
        s[i] = __ldg(src + ec);
        d[i] = __ldg(dst + ec);
    }

    uint4 va[KE], vb[KE];
#pragma unroll
    for (int i = 0; i < KE; i++) {
        va[i] = ldg_cg_128(g_A + (size_t)s[i] * HIDDEN + lane * 8);
        vb[i] = ldg_cg_128(g_B + (size_t)d[i] * HIDDEN + lane * 8);
    }

    const __half2 zero2 = __float2half2_rn(0.f);

#pragma unroll
    for (int i = 0; i < KE; i++) {
        const __half2* pa = (const __half2*)&va[i];
        const __half2* pb = (const __half2*)&vb[i];
        float acc = 0.f;
#pragma unroll
        for (int q = 0; q < 4; q++) {
            __half2 z2 = __hmax2(__hadd2(pa[q], pb[q]), zero2);
            float2 f = __half22float2(z2);
            acc = fmaf(f.x, w[2 * q + 0], acc);
            acc = fmaf(f.y, w[2 * q + 1], acc);
        }
#pragma unroll
        for (int off = 16; off > 0; off >>= 1)
            acc += __shfl_xor_sync(0xFFFFFFFFu, acc, off);
        if (lane == 0 && (eb + i) < E) out[eb + i] = acc + sb2;
    }
}

// ---------------------------------------------------------------------------
extern "C" void kernel_launch(void* const* d_in, const int* in_sizes, int n_in,
                              void* d_out, int out_size)
{
    const float* h    = (const float*)d_in[0];
    const int*   src  = (const int*)d_in[1];
    const int*   dst  = (const int*)d_in[2];
    const float* W1_w = (const float*)d_in[3];
    const float* W1_b = (const float*)d_in[4];
    const float* W2_w = (const float*)d_in[5];
    const float* W2_b = (const float*)d_in[6];
    float* out = (float*)d_out;

    int n_nodes = in_sizes[0] / D_FEAT;
    int E = in_sizes[1];

    // 1) Weight reorder
    prep_w_kernel<<<(D_FEAT * NOUT + 255) / 256, 256>>>(W1_w);

    // 2) Precompute A' (with b1) and B per node — 102 KB dynamic smem
    static int smem_set = 0;
    int smem_bytes = 3 * TILE_B;
    if (!smem_set) {
        cudaFuncSetAttribute(gemm_ab_kernel,
                             cudaFuncAttributeMaxDynamicSharedMemorySize,
                             smem_bytes);
        smem_set = 1;
    }
    gemm_ab_kernel<<<(n_nodes + MT - 1) / MT, 256, smem_bytes>>>(h, W1_b, n_nodes);

    // 3) Per-edge: gather, add, relu, dot (32 edges per block)
    int edges_per_block = 8 * KE;
    edge_kernel<<<(E + edges_per_block - 1) / edges_per_block, 256>>>(
        src, dst, W2_w, W2_b, out, E);
}